// round 1
// baseline (speedup 1.0000x reference)
#include <cuda_runtime.h>
#include <cuda_bf16.h>

// InterLayerTrajectoryFlow: fused diff -> normalize -> causal 6-tap weighted sum.
// emb: [B, S, D] fp32, S=8192, D=512. Output same shape.
//
// Strategy: one block per (batch, 32-position chunk). 512 threads = 1 per column.
//  Phase 1: stream chunk+halo rows, form consecutive diffs into smem.
//  Phase 2: warp-per-row reduction -> inverse norms.
//  Phase 3: fuse weights * inv-norm * depth_scale into 6 coeffs per position.
//  Phase 4: sliding 6-register window, 6 FMAs per output element, coalesced store.

#define S_LEN 8192
#define D_DIM 512
#define P_CHUNK 32
#define E_ROWS (P_CHUNK + 6)   // 38 embedding rows (chunk + halo)
#define D_ROWS (P_CHUNK + 5)   // 37 diff rows
#define WIN 6

#define SMEM_FLOATS (D_ROWS * D_DIM + 40 + P_CHUNK * WIN)
#define SMEM_BYTES (SMEM_FLOATS * 4)

__global__ __launch_bounds__(512, 2)
void traj_flow_kernel(const float* __restrict__ emb,
                      const int* __restrict__ layer_idx,
                      float* __restrict__ out,
                      int B) {
    extern __shared__ float sm[];
    float* sdiff = sm;                         // [D_ROWS][D_DIM]
    float* srinv = sm + D_ROWS * D_DIM;        // [D_ROWS] (padded to 40)
    float* scw   = srinv + 40;                 // [P_CHUNK][WIN]

    const int col  = threadIdx.x;              // 0..511
    const int b    = blockIdx.y;
    const int pos0 = blockIdx.x * P_CHUNK;

    // ---------- Phase 1: load rows (with front halo), write diffs to smem ----------
    {
        const int gr0 = pos0 - WIN;            // first embedding row (may be < 0)
        const float* ep = emb + ((long long)(b * S_LEN + gr0)) * D_DIM + col;
        float prev = 0.0f;
        #pragma unroll
        for (int r = 0; r < E_ROWS; ++r) {
            float cur = (gr0 + r >= 0) ? ep[r * D_DIM] : 0.0f;
            if (r > 0) sdiff[(r - 1) * D_DIM + col] = cur - prev;
            prev = cur;
        }
    }
    __syncthreads();

    // ---------- Phase 2: per-diff-row squared-norm reduction -> inverse norm ----------
    {
        const int wid  = threadIdx.x >> 5;
        const int lane = threadIdx.x & 31;
        for (int row = wid; row < D_ROWS; row += 16) {
            const float* rp = sdiff + row * D_DIM;
            float s = 0.0f;
            #pragma unroll
            for (int j = 0; j < D_DIM / 32; ++j) {
                float v = rp[lane + j * 32];
                s = fmaf(v, v, s);
            }
            #pragma unroll
            for (int o = 16; o > 0; o >>= 1)
                s += __shfl_xor_sync(0xffffffffu, s, o);
            if (lane == 0) {
                float mag = sqrtf(s);
                srinv[row] = (mag > 1e-6f) ? (1.0f / (mag + 1e-8f)) : 0.0f;
            }
        }
    }
    __syncthreads();

    // ---------- Phase 3: fused coefficients cw[lp][k] ----------
    if (threadIdx.x < P_CHUNK * WIN) {
        const int lp  = threadIdx.x / WIN;
        const int k   = threadIdx.x % WIN;
        const int pos = pos0 + lp;
        float c = 0.0f;
        const int w = (pos < WIN) ? pos : WIN;
        if (pos >= 1 && k < w) {
            const float ds = 0.1f * (1.0f + (float)(*layer_idx) * 0.8f);
            float Wk, wsum;
            if (w == 1) {
                Wk = expf(-1.0f);
                wsum = Wk;
            } else {
                const float dn = (float)(w - 1);
                wsum = 0.0f;
                for (int j = 0; j < w; ++j) wsum += expf(-(float)j / dn);
                Wk = expf(-(float)k / dn);
            }
            // diff used: global index pos-1-k -> local index lp + 5 - k
            c = Wk / (wsum + 1e-8f) * ds * srinv[lp + 5 - k];
        }
        scw[threadIdx.x] = c;
    }
    __syncthreads();

    // ---------- Phase 4: sliding-window weighted sum, coalesced store ----------
    {
        float win[WIN];
        #pragma unroll
        for (int i = 0; i < WIN; ++i) win[i] = sdiff[i * D_DIM + col];

        float* op = out + ((long long)(b * S_LEN + pos0)) * D_DIM + col;
        #pragma unroll
        for (int lp = 0; lp < P_CHUNK; ++lp) {
            float acc = 0.0f;
            // term k uses diffs[lp + 5 - k] = win[5 - k]
            #pragma unroll
            for (int k = 0; k < WIN; ++k)
                acc = fmaf(scw[lp * WIN + k], win[5 - k], acc);
            op[lp * D_DIM] = acc;
            #pragma unroll
            for (int i = 0; i < WIN - 1; ++i) win[i] = win[i + 1];
            if (lp < P_CHUNK - 1)
                win[WIN - 1] = sdiff[(lp + WIN) * D_DIM + col];
        }
    }
}

extern "C" void kernel_launch(void* const* d_in, const int* in_sizes, int n_in,
                              void* d_out, int out_size) {
    const float* emb = (const float*)d_in[0];
    const int* layer_idx = (const int*)d_in[1];
    float* out = (float*)d_out;

    const int B = in_sizes[0] / (S_LEN * D_DIM);

    cudaFuncSetAttribute(traj_flow_kernel,
                         cudaFuncAttributeMaxDynamicSharedMemorySize, SMEM_BYTES);

    dim3 grid(S_LEN / P_CHUNK, B);
    traj_flow_kernel<<<grid, D_DIM, SMEM_BYTES>>>(emb, layer_idx, out, B);
}